// round 2
// baseline (speedup 1.0000x reference)
#include <cuda_runtime.h>

// Problem constants
#define TT 128
#define BB 512
#define DD 768

typedef unsigned long long ull;

// Scratch (device globals — no runtime allocation allowed)
__device__ float g_G[(size_t)TT * BB * 64];  // gates [t][b][64]: 0-31 fwd, 32-63 bwd (bias included)
__device__ float g_h[(size_t)TT * BB * 16];  // bi-LSTM hidden [t][b][16]
__device__ float g_z[(size_t)TT * BB * 16];  // ptr-LSTM hidden [t][b][16]

__device__ __forceinline__ float sigmoidf_fast(float x) {
    return 1.0f / (1.0f + __expf(-x));
}

// ---- packed f32x2 helpers (sm_103a full-rate fp32 path) ----
__device__ __forceinline__ ull fma2_(ull a, ull b, ull c) {
    ull d;
    asm("fma.rn.f32x2 %0, %1, %2, %3;" : "=l"(d) : "l"(a), "l"(b), "l"(c));
    return d;
}
__device__ __forceinline__ ull pack2(float x) {
    ull d;
    asm("mov.b64 %0, {%1, %1};" : "=l"(d) : "f"(x));
    return d;
}
__device__ __forceinline__ float2 unpk(ull v) {
    float lo, hi;
    asm("mov.b64 {%0, %1}, %2;" : "=f"(lo), "=f"(hi) : "l"(v));
    return make_float2(lo, hi);
}
__device__ __forceinline__ float hsum2(ull v) {
    float2 t = unpk(v);
    return t.x + t.y;
}

// ---------------------------------------------------------------------------
// K1: fused input projection, G = X @ Wcat^T + bias.  X: 65536x768,
// Wcat: 64x768 (rows 0-31 Wih_f, 32-63 Wih_b).
// Full W transposed in smem (ws[k][j], 192KB, broadcast reads). X staged in
// 8-wide K chunks. 256 threads, each owns 2 rows x 64 cols, FFMA2 packed
// over adjacent j. 128 blocks = one wave.
// ---------------------------------------------------------------------------
#define K1_WS_FLOATS (DD * 64)          // 49152
#define K1_XS_STRIDE 12                 // 8 floats + pad, 48B rows (16B aligned)
#define K1_XS_FLOATS (512 * K1_XS_STRIDE)
#define K1_SMEM_FLOATS (K1_WS_FLOATS + K1_XS_FLOATS + 64)
#define K1_SMEM_BYTES (K1_SMEM_FLOATS * 4)

extern __shared__ float k1_smem[];

__global__ __launch_bounds__(256, 1) void k1_proj(
    const float* __restrict__ X,
    const float* __restrict__ Wf, const float* __restrict__ Wb,
    const float* __restrict__ bf1, const float* __restrict__ bf2,
    const float* __restrict__ bb1, const float* __restrict__ bb2)
{
    float* ws   = k1_smem;                     // [768][64]
    float* xs   = ws + K1_WS_FLOATS;           // [512][12]
    float* bias = xs + K1_XS_FLOATS;           // [64]

    const int tid = threadIdx.x;

    if (tid < 64)
        bias[tid] = (tid < 32) ? (bf1[tid] + bf2[tid])
                               : (bb1[tid - 32] + bb2[tid - 32]);

    // Transposed W load: thread owns column j = tid&63, quarter of k-range.
    {
        int j = tid & 63;
        int part = tid >> 6;
        const float* wrow = (j < 32) ? (Wf + (size_t)j * DD)
                                     : (Wb + (size_t)(j - 32) * DD);
#pragma unroll 4
        for (int kq = part * 48; kq < part * 48 + 48; kq++) {
            float4 v = *(const float4*)(wrow + kq * 4);
            ws[(kq * 4 + 0) * 64 + j] = v.x;
            ws[(kq * 4 + 1) * 64 + j] = v.y;
            ws[(kq * 4 + 2) * 64 + j] = v.z;
            ws[(kq * 4 + 3) * 64 + j] = v.w;
        }
    }

    const int r0 = blockIdx.x * 512;
    const int row_a = 2 * tid;
    const int row_b = 2 * tid + 1;

    ull acc0[32], acc1[32];
#pragma unroll
    for (int i = 0; i < 32; i++) { acc0[i] = 0ull; acc1[i] = 0ull; }

    for (int s = 0; s < 96; s++) {
        const int k0 = s * 8;
        __syncthreads();   // xs reuse guard (also covers initial ws fill)
        // stage X: 512 rows x 8 floats, coalesced 32B pairs
#pragma unroll
        for (int v = 0; v < 4; v++) {
            int idx = v * 256 + tid;
            int row = idx >> 1;
            int c = idx & 1;
            float4 xv = *(const float4*)(X + (size_t)(r0 + row) * DD + k0 + c * 4);
            *(float4*)(xs + row * K1_XS_STRIDE + c * 4) = xv;
        }
        __syncthreads();

        float xa[8], xb[8];
        *(float4*)&xa[0] = *(const float4*)(xs + row_a * K1_XS_STRIDE);
        *(float4*)&xa[4] = *(const float4*)(xs + row_a * K1_XS_STRIDE + 4);
        *(float4*)&xb[0] = *(const float4*)(xs + row_b * K1_XS_STRIDE);
        *(float4*)&xb[4] = *(const float4*)(xs + row_b * K1_XS_STRIDE + 4);

#pragma unroll
        for (int k = 0; k < 8; k++) {
            ull xa2 = pack2(xa[k]);
            ull xb2 = pack2(xb[k]);
            const ulonglong2* wrow2 = (const ulonglong2*)(ws + (k0 + k) * 64);
#pragma unroll
            for (int i = 0; i < 16; i++) {
                ulonglong2 w = wrow2[i];
                acc0[2 * i]     = fma2_(xa2, w.x, acc0[2 * i]);
                acc0[2 * i + 1] = fma2_(xa2, w.y, acc0[2 * i + 1]);
                acc1[2 * i]     = fma2_(xb2, w.x, acc1[2 * i]);
                acc1[2 * i + 1] = fma2_(xb2, w.y, acc1[2 * i + 1]);
            }
        }
    }

    // epilogue: bias + store (16B stores per 4 j)
    float* ga = g_G + (size_t)(r0 + row_a) * 64;
    float* gb = g_G + (size_t)(r0 + row_b) * 64;
#pragma unroll
    for (int i = 0; i < 16; i++) {
        float b0 = bias[4 * i + 0], b1 = bias[4 * i + 1];
        float b2 = bias[4 * i + 2], b3 = bias[4 * i + 3];
        float2 p0 = unpk(acc0[2 * i]), p1 = unpk(acc0[2 * i + 1]);
        float4 oa = make_float4(p0.x + b0, p0.y + b1, p1.x + b2, p1.y + b3);
        *(float4*)(ga + 4 * i) = oa;
        float2 q0 = unpk(acc1[2 * i]), q1 = unpk(acc1[2 * i + 1]);
        float4 ob = make_float4(q0.x + b0, q0.y + b1, q1.x + b2, q1.y + b3);
        *(float4*)(gb + 4 * i) = ob;
    }
}

// ---------------------------------------------------------------------------
// K2: bi-LSTM scans (fwd + bwd), one warp per (batch item, direction).
// ---------------------------------------------------------------------------
__global__ __launch_bounds__(128) void k2_bilstm(
    const float* __restrict__ Whhf, const float* __restrict__ Whhb)
{
    const unsigned FULL = 0xffffffffu;
    int warp = blockIdx.x * (blockDim.x >> 5) + (threadIdx.x >> 5); // 0..1023
    int lane = threadIdx.x & 31;
    int dir  = warp >> 9;
    int b    = warp & 511;

    const float* Whh = dir ? Whhb : Whhf;
    float w[8];
#pragma unroll
    for (int k = 0; k < 8; k++) w[k] = Whh[lane * 8 + k];

    float hrep[8];
#pragma unroll
    for (int k = 0; k < 8; k++) hrep[k] = 0.0f;
    float c = 0.0f;

    const int coloff = dir * 32 + lane;
    int t0 = dir ? (TT - 1) : 0;
    float gcur = g_G[((size_t)t0 * BB + b) * 64 + coloff];

    for (int s = 0; s < TT; s++) {
        int t = dir ? (TT - 1 - s) : s;
        float gnext = 0.0f;
        if (s + 1 < TT) {
            int tn = dir ? (TT - 2 - s) : (s + 1);
            gnext = g_G[((size_t)tn * BB + b) * 64 + coloff];
        }
        float gate = gcur;
#pragma unroll
        for (int k = 0; k < 8; k++) gate = fmaf(hrep[k], w[k], gate);

        float a = (lane >= 16 && lane < 24) ? tanhf(gate) : sigmoidf_fast(gate);
        float fv = __shfl_sync(FULL, a, lane + 8);
        float gv = __shfl_sync(FULL, a, lane + 16);
        float ov = __shfl_sync(FULL, a, lane + 24);

        float hnew = 0.0f;
        if (lane < 8) {
            c = fmaf(fv, c, a * gv);
            hnew = ov * tanhf(c);
            g_h[((size_t)t * BB + b) * 16 + dir * 8 + lane] = hnew;
        }
#pragma unroll
        for (int k = 0; k < 8; k++) hrep[k] = __shfl_sync(FULL, hnew, k);
        gcur = gnext;
    }
}

// ---------------------------------------------------------------------------
// K4: ptr-LSTM scan, one warp per batch item.
// ---------------------------------------------------------------------------
__global__ __launch_bounds__(128) void k4_ptr(
    const float* __restrict__ Wih, const float* __restrict__ Whh,
    const float* __restrict__ b1, const float* __restrict__ b2)
{
    const unsigned FULL = 0xffffffffu;
    int warp = blockIdx.x * (blockDim.x >> 5) + (threadIdx.x >> 5); // 0..511
    int lane = threadIdx.x & 31;
    int b    = warp;

    const int r0 = lane, r1 = lane + 32;
    float wi0[16], wi1[16], wh0[16], wh1[16];
#pragma unroll
    for (int k = 0; k < 16; k++) {
        wi0[k] = Wih[r0 * 16 + k];
        wi1[k] = Wih[r1 * 16 + k];
        wh0[k] = Whh[r0 * 16 + k];
        wh1[k] = Whh[r1 * 16 + k];
    }
    const float bias0 = b1[r0] + b2[r0];
    const float bias1 = b1[r1] + b2[r1];

    float zrep[16];
#pragma unroll
    for (int k = 0; k < 16; k++) zrep[k] = 0.0f;
    float c = 0.0f;

    const float4* hp = (const float4*)g_h;
    size_t base = ((size_t)0 * BB + b) * 4;
    float4 x0 = hp[base + 0], x1 = hp[base + 1], x2 = hp[base + 2], x3 = hp[base + 3];

    for (int t = 0; t < TT; t++) {
        float4 n0 = x0, n1 = x1, n2 = x2, n3 = x3;
        if (t + 1 < TT) {
            size_t nb = ((size_t)(t + 1) * BB + b) * 4;
            n0 = hp[nb + 0]; n1 = hp[nb + 1]; n2 = hp[nb + 2]; n3 = hp[nb + 3];
        }
        float xin[16] = {x0.x, x0.y, x0.z, x0.w, x1.x, x1.y, x1.z, x1.w,
                         x2.x, x2.y, x2.z, x2.w, x3.x, x3.y, x3.z, x3.w};
        float u0 = bias0, u1 = bias1;
#pragma unroll
        for (int k = 0; k < 16; k++) {
            u0 = fmaf(xin[k], wi0[k], u0);
            u1 = fmaf(xin[k], wi1[k], u1);
        }
#pragma unroll
        for (int k = 0; k < 16; k++) {
            u0 = fmaf(zrep[k], wh0[k], u0);
            u1 = fmaf(zrep[k], wh1[k], u1);
        }
        float a0 = sigmoidf_fast(u0);
        float a1 = (lane < 16) ? tanhf(u1) : sigmoidf_fast(u1);
        float fv = __shfl_sync(FULL, a0, lane + 16);
        float ov = __shfl_sync(FULL, a1, lane + 16);

        float zn = 0.0f;
        if (lane < 16) {
            c = fmaf(fv, c, a0 * a1);
            zn = ov * tanhf(c);
            g_z[((size_t)t * BB + b) * 16 + lane] = zn;
        }
#pragma unroll
        for (int k = 0; k < 16; k++) zrep[k] = __shfl_sync(FULL, zn, k);
        x0 = n0; x1 = n1; x2 = n2; x3 = n3;
    }
}

// ---------------------------------------------------------------------------
// K5: per-timestep attention + scoring (f32x2 packed). One block per t,
// 512 threads (thread = query row b). Scores bounded (|S|<=16): no max pass.
// ---------------------------------------------------------------------------
#define K5_EPAD 520
#define K5_SMEM_FLOATS (8192 + 8192 + 64 * K5_EPAD + 512 + 64 + 528)
#define K5_SMEM_BYTES  (K5_SMEM_FLOATS * 4)

extern __shared__ float k5_smem[];

__global__ __launch_bounds__(512, 1) void k5_attn(
    const float* __restrict__ Wh, const float* __restrict__ We,
    const float* __restrict__ Wv, float* __restrict__ out)
{
    float* hs  = k5_smem;                  // 512*16
    float* zs  = hs + 8192;                // 512*16
    float* E   = zs + 8192;                // 64 * 520
    float* red = E + 64 * K5_EPAD;         // 512
    float* inv = red + 512;                // 64
    float* ws  = inv + 64;                 // Wh[256] | We[256] | Wv[16]

    const int tid = threadIdx.x;
    const int t   = blockIdx.x;

    const float4* hg = (const float4*)(g_h + (size_t)t * BB * 16);
    const float4* zg = (const float4*)(g_z + (size_t)t * BB * 16);
    float4* hs4 = (float4*)hs;
    float4* zs4 = (float4*)zs;
#pragma unroll
    for (int i = 0; i < 4; i++) {
        hs4[i * 512 + tid] = hg[i * 512 + tid];
        zs4[i * 512 + tid] = zg[i * 512 + tid];
    }
    if (tid < 256) ws[tid] = Wh[tid];
    else           ws[tid] = We[tid - 256];
    if (tid < 16)  ws[512 + tid] = Wv[tid];
    __syncthreads();

    const int bq = tid;
    ull hr2[8];
    {
        const ulonglong2* hp = (const ulonglong2*)(hs + bq * 16);
#pragma unroll
        for (int i = 0; i < 4; i++) {
            ulonglong2 v = hp[i];
            hr2[2 * i] = v.x; hr2[2 * i + 1] = v.y;
        }
    }
    ull ctx2[8];
#pragma unroll
    for (int d = 0; d < 8; d++) ctx2[d] = 0ull;

    for (int tile = 0; tile < 8; tile++) {
        // --- scores + exp for 64 softmax-columns ---
#pragma unroll 4
        for (int cc = 0; cc < 64; cc++) {
            const ulonglong2* zp = (const ulonglong2*)(zs + (tile * 64 + cc) * 16);
            ulonglong2 z0 = zp[0], z1 = zp[1], z2 = zp[2], z3 = zp[3];
            ull d2 = 0ull;
            d2 = fma2_(hr2[0], z0.x, d2);
            d2 = fma2_(hr2[1], z0.y, d2);
            d2 = fma2_(hr2[2], z1.x, d2);
            d2 = fma2_(hr2[3], z1.y, d2);
            d2 = fma2_(hr2[4], z2.x, d2);
            d2 = fma2_(hr2[5], z2.y, d2);
            d2 = fma2_(hr2[6], z3.x, d2);
            d2 = fma2_(hr2[7], z3.y, d2);
            E[cc * K5_EPAD + bq] = __expf(hsum2(d2));
        }
        __syncthreads();
        // --- column sums (over b) ---
        {
            int cc = tid >> 3, seg = tid & 7;
            float s = 0.0f;
#pragma unroll 8
            for (int j = 0; j < 64; j++) s += E[cc * K5_EPAD + seg + 8 * j];
            red[tid] = s;
        }
        __syncthreads();
        if (tid < 64) {
            float s = 0.0f;
#pragma unroll
            for (int r = 0; r < 8; r++) s += red[tid * 8 + r];
            inv[tid] = 1.0f / s;
        }
        __syncthreads();
        // --- context accumulation (E reads done before next tile's writes) ---
#pragma unroll 4
        for (int cc = 0; cc < 64; cc++) {
            float wv = E[cc * K5_EPAD + bq] * inv[cc];
            ull wv2 = pack2(wv);
            const ulonglong2* hp2 = (const ulonglong2*)(hs + (tile * 64 + cc) * 16);
            ulonglong2 h0 = hp2[0], h1 = hp2[1], h2 = hp2[2], h3 = hp2[3];
            ctx2[0] = fma2_(wv2, h0.x, ctx2[0]);
            ctx2[1] = fma2_(wv2, h0.y, ctx2[1]);
            ctx2[2] = fma2_(wv2, h1.x, ctx2[2]);
            ctx2[3] = fma2_(wv2, h1.y, ctx2[3]);
            ctx2[4] = fma2_(wv2, h2.x, ctx2[4]);
            ctx2[5] = fma2_(wv2, h2.y, ctx2[5]);
            ctx2[6] = fma2_(wv2, h3.x, ctx2[6]);
            ctx2[7] = fma2_(wv2, h3.y, ctx2[7]);
        }
        // sync happens at top of next tile's score phase via the one below
        __syncthreads();
    }

    // --- scoring epilogue: p = sigmoid( Wv . tanh(Wh h + We ctx) ) ---
    float hr[16], ctx[16];
#pragma unroll
    for (int d = 0; d < 8; d++) {
        float2 a = unpk(hr2[d]);  hr[2 * d] = a.x;  hr[2 * d + 1] = a.y;
        float2 b = unpk(ctx2[d]); ctx[2 * d] = b.x; ctx[2 * d + 1] = b.y;
    }
    float p = 0.0f;
#pragma unroll
    for (int d = 0; d < 16; d++) {
        float s = 0.0f;
#pragma unroll
        for (int e = 0; e < 16; e++) s = fmaf(hr[e], ws[d * 16 + e], s);
#pragma unroll
        for (int e = 0; e < 16; e++) s = fmaf(ctx[e], ws[256 + d * 16 + e], s);
        p = fmaf(tanhf(s), ws[512 + d], p);
    }
    out[(size_t)t * BB + bq] = sigmoidf_fast(p);
}

// ---------------------------------------------------------------------------
extern "C" void kernel_launch(void* const* d_in, const int* in_sizes, int n_in,
                              void* d_out, int out_size)
{
    const float* X     = (const float*)d_in[0];
    const float* Wih_f = (const float*)d_in[1];
    const float* Whh_f = (const float*)d_in[2];
    const float* bih_f = (const float*)d_in[3];
    const float* bhh_f = (const float*)d_in[4];
    const float* Wih_b = (const float*)d_in[5];
    const float* Whh_b = (const float*)d_in[6];
    const float* bih_b = (const float*)d_in[7];
    const float* bhh_b = (const float*)d_in[8];
    const float* Wih_p = (const float*)d_in[9];
    const float* Whh_p = (const float*)d_in[10];
    const float* bih_p = (const float*)d_in[11];
    const float* bhh_p = (const float*)d_in[12];
    const float* W_h   = (const float*)d_in[13];
    const float* W_e   = (const float*)d_in[14];
    const float* W_v   = (const float*)d_in[15];
    float* out = (float*)d_out;

    cudaFuncSetAttribute(k1_proj, cudaFuncAttributeMaxDynamicSharedMemorySize,
                         K1_SMEM_BYTES);
    cudaFuncSetAttribute(k5_attn, cudaFuncAttributeMaxDynamicSharedMemorySize,
                         K5_SMEM_BYTES);

    k1_proj<<<128, 256, K1_SMEM_BYTES>>>(X, Wih_f, Wih_b, bih_f, bhh_f, bih_b, bhh_b);
    k2_bilstm<<<256, 128>>>(Whh_f, Whh_b);
    k4_ptr<<<128, 128>>>(Wih_p, Whh_p, bih_p, bhh_p);
    k5_attn<<<TT, 512, K5_SMEM_BYTES>>>(W_h, W_e, W_v, out);
}

// round 3
// speedup vs baseline: 1.2175x; 1.2175x over previous
#include <cuda_runtime.h>

// Problem constants
#define TT 128
#define BB 512
#define DD 768

typedef unsigned long long ull;

// Scratch (device globals — no runtime allocation allowed)
__device__ float g_G[(size_t)TT * BB * 64];  // gates [t][b][64]: 0-31 fwd, 32-63 bwd (bias included)
__device__ float g_h[(size_t)TT * BB * 16];  // bi-LSTM hidden [t][b][16]
__device__ float g_z[(size_t)TT * BB * 16];  // ptr-LSTM hidden [t][b][16]

__device__ __forceinline__ float sigmoidf_fast(float x) {
    return 1.0f / (1.0f + __expf(-x));
}

// ---- packed f32x2 helpers (sm_103a full-rate fp32 path) ----
__device__ __forceinline__ ull fma2_(ull a, ull b, ull c) {
    ull d;
    asm("fma.rn.f32x2 %0, %1, %2, %3;" : "=l"(d) : "l"(a), "l"(b), "l"(c));
    return d;
}
__device__ __forceinline__ ull pack2(float x) {
    ull d;
    asm("mov.b64 %0, {%1, %1};" : "=l"(d) : "f"(x));
    return d;
}
__device__ __forceinline__ float2 unpk(ull v) {
    float lo, hi;
    asm("mov.b64 {%0, %1}, %2;" : "=f"(lo), "=f"(hi) : "l"(v));
    return make_float2(lo, hi);
}
__device__ __forceinline__ float hsum2(ull v) {
    float2 t = unpk(v);
    return t.x + t.y;
}

// ---------------------------------------------------------------------------
// K1: fused input projection, G = X @ Wcat^T + bias.
// X: 65536x768, Wcat: 64x768 (rows 0-31 Wih_f, 32-63 Wih_b).
// grid 256, 128 thr, BM=256 BN=64 BK=8, microtile 8 rows x 16 cols (f32x2),
// single-buffer smem with register prefetch. Compute-bound by design:
// per k per thread 6 LDS.128 (24 smem-cyc/warp) vs 64 FFMA2 (32 issue-cyc).
// ---------------------------------------------------------------------------
__global__ __launch_bounds__(128) void k1_proj(
    const float* __restrict__ X,
    const float* __restrict__ Wf, const float* __restrict__ Wb,
    const float* __restrict__ bf1, const float* __restrict__ bf2,
    const float* __restrict__ bb1, const float* __restrict__ bb2)
{
    __shared__ float As[8][256];   // [k][m] 8KB
    __shared__ float Bs[8][64];    // [k][n] 2KB
    __shared__ float bias[64];

    const int tid = threadIdx.x;
    const int r0  = blockIdx.x * 256;
    const int ty  = tid >> 2;      // 0..31 -> rows ty*8 .. +7
    const int tx  = tid & 3;       // 0..3  -> cols tx*16 .. +15

    if (tid < 64)
        bias[tid] = (tid < 32) ? (bf1[tid] + bf2[tid])
                               : (bb1[tid - 32] + bb2[tid - 32]);

    // staging pointers
    const float* xrow0 = X + (size_t)(r0 + tid) * DD;         // row tid
    const float* xrow1 = X + (size_t)(r0 + tid + 128) * DD;   // row tid+128
    const int wj = tid >> 1;            // 0..63 (gate col)
    const int wh = tid & 1;             // which half of the 8-k chunk
    const float* wrow = ((wj < 32) ? (Wf + (size_t)wj * DD)
                                   : (Wb + (size_t)(wj - 32) * DD)) + wh * 4;

    // prefetch tile 0
    float4 xa0 = *(const float4*)(xrow0 + 0);
    float4 xa1 = *(const float4*)(xrow0 + 4);
    float4 xb0 = *(const float4*)(xrow1 + 0);
    float4 xb1 = *(const float4*)(xrow1 + 4);
    float4 wv  = *(const float4*)(wrow + 0);

    ull acc[8][8];
#pragma unroll
    for (int r = 0; r < 8; r++)
#pragma unroll
        for (int c = 0; c < 8; c++) acc[r][c] = 0ull;

    for (int s = 0; s < 96; s++) {
        __syncthreads();
        // commit staged registers to smem
        As[0][tid] = xa0.x; As[1][tid] = xa0.y; As[2][tid] = xa0.z; As[3][tid] = xa0.w;
        As[4][tid] = xa1.x; As[5][tid] = xa1.y; As[6][tid] = xa1.z; As[7][tid] = xa1.w;
        As[0][tid + 128] = xb0.x; As[1][tid + 128] = xb0.y;
        As[2][tid + 128] = xb0.z; As[3][tid + 128] = xb0.w;
        As[4][tid + 128] = xb1.x; As[5][tid + 128] = xb1.y;
        As[6][tid + 128] = xb1.z; As[7][tid + 128] = xb1.w;
        Bs[wh * 4 + 0][wj] = wv.x; Bs[wh * 4 + 1][wj] = wv.y;
        Bs[wh * 4 + 2][wj] = wv.z; Bs[wh * 4 + 3][wj] = wv.w;
        __syncthreads();

        // prefetch next tile (hidden under the FMA block below)
        if (s + 1 < 96) {
            const int kn = (s + 1) * 8;
            xa0 = *(const float4*)(xrow0 + kn);
            xa1 = *(const float4*)(xrow0 + kn + 4);
            xb0 = *(const float4*)(xrow1 + kn);
            xb1 = *(const float4*)(xrow1 + kn + 4);
            wv  = *(const float4*)(wrow + kn);
        }

#pragma unroll
        for (int k = 0; k < 8; k++) {
            float xv[8];
            *(float4*)&xv[0] = *(const float4*)&As[k][ty * 8];
            *(float4*)&xv[4] = *(const float4*)&As[k][ty * 8 + 4];
            ull w2[8];
            {
                const ulonglong2* wp = (const ulonglong2*)&Bs[k][tx * 16];
                ulonglong2 a = wp[0], b = wp[1], c = wp[2], d = wp[3];
                w2[0] = a.x; w2[1] = a.y; w2[2] = b.x; w2[3] = b.y;
                w2[4] = c.x; w2[5] = c.y; w2[6] = d.x; w2[7] = d.y;
            }
#pragma unroll
            for (int r = 0; r < 8; r++) {
                ull x2 = pack2(xv[r]);
#pragma unroll
                for (int c = 0; c < 8; c++)
                    acc[r][c] = fma2_(x2, w2[c], acc[r][c]);
            }
        }
    }

    // epilogue: bias + 4x float4 stores per row
    float bl[16];
#pragma unroll
    for (int i = 0; i < 16; i++) bl[i] = bias[tx * 16 + i];
#pragma unroll
    for (int r = 0; r < 8; r++) {
        float* gp = g_G + (size_t)(r0 + ty * 8 + r) * 64 + tx * 16;
#pragma unroll
        for (int q = 0; q < 4; q++) {
            float2 p0 = unpk(acc[r][2 * q]);
            float2 p1 = unpk(acc[r][2 * q + 1]);
            float4 o = make_float4(p0.x + bl[4 * q + 0], p0.y + bl[4 * q + 1],
                                   p1.x + bl[4 * q + 2], p1.y + bl[4 * q + 3]);
            *(float4*)(gp + 4 * q) = o;
        }
    }
}

// ---------------------------------------------------------------------------
// K2: bi-LSTM scans (fwd + bwd), one warp per (batch item, direction).
// ---------------------------------------------------------------------------
__global__ __launch_bounds__(128) void k2_bilstm(
    const float* __restrict__ Whhf, const float* __restrict__ Whhb)
{
    const unsigned FULL = 0xffffffffu;
    int warp = blockIdx.x * (blockDim.x >> 5) + (threadIdx.x >> 5); // 0..1023
    int lane = threadIdx.x & 31;
    int dir  = warp >> 9;
    int b    = warp & 511;

    const float* Whh = dir ? Whhb : Whhf;
    float w[8];
#pragma unroll
    for (int k = 0; k < 8; k++) w[k] = Whh[lane * 8 + k];

    float hrep[8];
#pragma unroll
    for (int k = 0; k < 8; k++) hrep[k] = 0.0f;
    float c = 0.0f;

    const int coloff = dir * 32 + lane;
    int t0 = dir ? (TT - 1) : 0;
    float gcur = g_G[((size_t)t0 * BB + b) * 64 + coloff];

    for (int s = 0; s < TT; s++) {
        int t = dir ? (TT - 1 - s) : s;
        float gnext = 0.0f;
        if (s + 1 < TT) {
            int tn = dir ? (TT - 2 - s) : (s + 1);
            gnext = g_G[((size_t)tn * BB + b) * 64 + coloff];
        }
        float gate = gcur;
#pragma unroll
        for (int k = 0; k < 8; k++) gate = fmaf(hrep[k], w[k], gate);

        float a = (lane >= 16 && lane < 24) ? tanhf(gate) : sigmoidf_fast(gate);
        float fv = __shfl_sync(FULL, a, lane + 8);
        float gv = __shfl_sync(FULL, a, lane + 16);
        float ov = __shfl_sync(FULL, a, lane + 24);

        float hnew = 0.0f;
        if (lane < 8) {
            c = fmaf(fv, c, a * gv);
            hnew = ov * tanhf(c);
            g_h[((size_t)t * BB + b) * 16 + dir * 8 + lane] = hnew;
        }
#pragma unroll
        for (int k = 0; k < 8; k++) hrep[k] = __shfl_sync(FULL, hnew, k);
        gcur = gnext;
    }
}

// ---------------------------------------------------------------------------
// K4: ptr-LSTM scan, one warp per batch item.
// ---------------------------------------------------------------------------
__global__ __launch_bounds__(128) void k4_ptr(
    const float* __restrict__ Wih, const float* __restrict__ Whh,
    const float* __restrict__ b1, const float* __restrict__ b2)
{
    const unsigned FULL = 0xffffffffu;
    int warp = blockIdx.x * (blockDim.x >> 5) + (threadIdx.x >> 5); // 0..511
    int lane = threadIdx.x & 31;
    int b    = warp;

    const int r0 = lane, r1 = lane + 32;
    float wi0[16], wi1[16], wh0[16], wh1[16];
#pragma unroll
    for (int k = 0; k < 16; k++) {
        wi0[k] = Wih[r0 * 16 + k];
        wi1[k] = Wih[r1 * 16 + k];
        wh0[k] = Whh[r0 * 16 + k];
        wh1[k] = Whh[r1 * 16 + k];
    }
    const float bias0 = b1[r0] + b2[r0];
    const float bias1 = b1[r1] + b2[r1];

    float zrep[16];
#pragma unroll
    for (int k = 0; k < 16; k++) zrep[k] = 0.0f;
    float c = 0.0f;

    const float4* hp = (const float4*)g_h;
    size_t base = ((size_t)0 * BB + b) * 4;
    float4 x0 = hp[base + 0], x1 = hp[base + 1], x2 = hp[base + 2], x3 = hp[base + 3];

    for (int t = 0; t < TT; t++) {
        float4 n0 = x0, n1 = x1, n2 = x2, n3 = x3;
        if (t + 1 < TT) {
            size_t nb = ((size_t)(t + 1) * BB + b) * 4;
            n0 = hp[nb + 0]; n1 = hp[nb + 1]; n2 = hp[nb + 2]; n3 = hp[nb + 3];
        }
        float xin[16] = {x0.x, x0.y, x0.z, x0.w, x1.x, x1.y, x1.z, x1.w,
                         x2.x, x2.y, x2.z, x2.w, x3.x, x3.y, x3.z, x3.w};
        float u0 = bias0, u1 = bias1;
#pragma unroll
        for (int k = 0; k < 16; k++) {
            u0 = fmaf(xin[k], wi0[k], u0);
            u1 = fmaf(xin[k], wi1[k], u1);
        }
#pragma unroll
        for (int k = 0; k < 16; k++) {
            u0 = fmaf(zrep[k], wh0[k], u0);
            u1 = fmaf(zrep[k], wh1[k], u1);
        }
        float a0 = sigmoidf_fast(u0);
        float a1 = (lane < 16) ? tanhf(u1) : sigmoidf_fast(u1);
        float fv = __shfl_sync(FULL, a0, lane + 16);
        float ov = __shfl_sync(FULL, a1, lane + 16);

        float zn = 0.0f;
        if (lane < 16) {
            c = fmaf(fv, c, a0 * a1);
            zn = ov * tanhf(c);
            g_z[((size_t)t * BB + b) * 16 + lane] = zn;
        }
#pragma unroll
        for (int k = 0; k < 16; k++) zrep[k] = __shfl_sync(FULL, zn, k);
        x0 = n0; x1 = n1; x2 = n2; x3 = n3;
    }
}

// ---------------------------------------------------------------------------
// K5: per-timestep attention + scoring (f32x2 packed). One block per t,
// 512 threads (thread = query row b). Scores bounded (|S|<=16): no max pass.
// ---------------------------------------------------------------------------
#define K5_EPAD 520
#define K5_SMEM_FLOATS (8192 + 8192 + 64 * K5_EPAD + 512 + 64 + 528)
#define K5_SMEM_BYTES  (K5_SMEM_FLOATS * 4)

extern __shared__ float k5_smem[];

__global__ __launch_bounds__(512, 1) void k5_attn(
    const float* __restrict__ Wh, const float* __restrict__ We,
    const float* __restrict__ Wv, float* __restrict__ out)
{
    float* hs  = k5_smem;                  // 512*16
    float* zs  = hs + 8192;                // 512*16
    float* E   = zs + 8192;                // 64 * 520
    float* red = E + 64 * K5_EPAD;         // 512
    float* inv = red + 512;                // 64
    float* ws  = inv + 64;                 // Wh[256] | We[256] | Wv[16]

    const int tid = threadIdx.x;
    const int t   = blockIdx.x;

    const float4* hg = (const float4*)(g_h + (size_t)t * BB * 16);
    const float4* zg = (const float4*)(g_z + (size_t)t * BB * 16);
    float4* hs4 = (float4*)hs;
    float4* zs4 = (float4*)zs;
#pragma unroll
    for (int i = 0; i < 4; i++) {
        hs4[i * 512 + tid] = hg[i * 512 + tid];
        zs4[i * 512 + tid] = zg[i * 512 + tid];
    }
    if (tid < 256) ws[tid] = Wh[tid];
    else           ws[tid] = We[tid - 256];
    if (tid < 16)  ws[512 + tid] = Wv[tid];
    __syncthreads();

    const int bq = tid;
    ull hr2[8];
    {
        const ulonglong2* hp = (const ulonglong2*)(hs + bq * 16);
#pragma unroll
        for (int i = 0; i < 4; i++) {
            ulonglong2 v = hp[i];
            hr2[2 * i] = v.x; hr2[2 * i + 1] = v.y;
        }
    }
    ull ctx2[8];
#pragma unroll
    for (int d = 0; d < 8; d++) ctx2[d] = 0ull;

    for (int tile = 0; tile < 8; tile++) {
        // --- scores + exp for 64 softmax-columns ---
#pragma unroll 4
        for (int cc = 0; cc < 64; cc++) {
            const ulonglong2* zp = (const ulonglong2*)(zs + (tile * 64 + cc) * 16);
            ulonglong2 z0 = zp[0], z1 = zp[1], z2 = zp[2], z3 = zp[3];
            ull d2 = 0ull;
            d2 = fma2_(hr2[0], z0.x, d2);
            d2 = fma2_(hr2[1], z0.y, d2);
            d2 = fma2_(hr2[2], z1.x, d2);
            d2 = fma2_(hr2[3], z1.y, d2);
            d2 = fma2_(hr2[4], z2.x, d2);
            d2 = fma2_(hr2[5], z2.y, d2);
            d2 = fma2_(hr2[6], z3.x, d2);
            d2 = fma2_(hr2[7], z3.y, d2);
            E[cc * K5_EPAD + bq] = __expf(hsum2(d2));
        }
        __syncthreads();
        // --- column sums (over b) ---
        {
            int cc = tid >> 3, seg = tid & 7;
            float s = 0.0f;
#pragma unroll 8
            for (int j = 0; j < 64; j++) s += E[cc * K5_EPAD + seg + 8 * j];
            red[tid] = s;
        }
        __syncthreads();
        if (tid < 64) {
            float s = 0.0f;
#pragma unroll
            for (int r = 0; r < 8; r++) s += red[tid * 8 + r];
            inv[tid] = 1.0f / s;
        }
        __syncthreads();
        // --- context accumulation ---
#pragma unroll 4
        for (int cc = 0; cc < 64; cc++) {
            float wv = E[cc * K5_EPAD + bq] * inv[cc];
            ull wv2 = pack2(wv);
            const ulonglong2* hp2 = (const ulonglong2*)(hs + (tile * 64 + cc) * 16);
            ulonglong2 h0 = hp2[0], h1 = hp2[1], h2 = hp2[2], h3 = hp2[3];
            ctx2[0] = fma2_(wv2, h0.x, ctx2[0]);
            ctx2[1] = fma2_(wv2, h0.y, ctx2[1]);
            ctx2[2] = fma2_(wv2, h1.x, ctx2[2]);
            ctx2[3] = fma2_(wv2, h1.y, ctx2[3]);
            ctx2[4] = fma2_(wv2, h2.x, ctx2[4]);
            ctx2[5] = fma2_(wv2, h2.y, ctx2[5]);
            ctx2[6] = fma2_(wv2, h3.x, ctx2[6]);
            ctx2[7] = fma2_(wv2, h3.y, ctx2[7]);
        }
        __syncthreads();
    }

    // --- scoring epilogue: p = sigmoid( Wv . tanh(Wh h + We ctx) ) ---
    float hr[16], ctx[16];
#pragma unroll
    for (int d = 0; d < 8; d++) {
        float2 a = unpk(hr2[d]);  hr[2 * d] = a.x;  hr[2 * d + 1] = a.y;
        float2 b = unpk(ctx2[d]); ctx[2 * d] = b.x; ctx[2 * d + 1] = b.y;
    }
    float p = 0.0f;
#pragma unroll
    for (int d = 0; d < 16; d++) {
        float s = 0.0f;
#pragma unroll
        for (int e = 0; e < 16; e++) s = fmaf(hr[e], ws[d * 16 + e], s);
#pragma unroll
        for (int e = 0; e < 16; e++) s = fmaf(ctx[e], ws[256 + d * 16 + e], s);
        p = fmaf(tanhf(s), ws[512 + d], p);
    }
    out[(size_t)t * BB + bq] = sigmoidf_fast(p);
}

// ---------------------------------------------------------------------------
extern "C" void kernel_launch(void* const* d_in, const int* in_sizes, int n_in,
                              void* d_out, int out_size)
{
    const float* X     = (const float*)d_in[0];
    const float* Wih_f = (const float*)d_in[1];
    const float* Whh_f = (const float*)d_in[2];
    const float* bih_f = (const float*)d_in[3];
    const float* bhh_f = (const float*)d_in[4];
    const float* Wih_b = (const float*)d_in[5];
    const float* Whh_b = (const float*)d_in[6];
    const float* bih_b = (const float*)d_in[7];
    const float* bhh_b = (const float*)d_in[8];
    const float* Wih_p = (const float*)d_in[9];
    const float* Whh_p = (const float*)d_in[10];
    const float* bih_p = (const float*)d_in[11];
    const float* bhh_p = (const float*)d_in[12];
    const float* W_h   = (const float*)d_in[13];
    const float* W_e   = (const float*)d_in[14];
    const float* W_v   = (const float*)d_in[15];
    float* out = (float*)d_out;

    cudaFuncSetAttribute(k5_attn, cudaFuncAttributeMaxDynamicSharedMemorySize,
                         K5_SMEM_BYTES);

    k1_proj<<<256, 128>>>(X, Wih_f, Wih_b, bih_f, bhh_f, bih_b, bhh_b);
    k2_bilstm<<<256, 128>>>(Whh_f, Whh_b);
    k4_ptr<<<128, 128>>>(Wih_p, Whh_p, bih_p, bhh_p);
    k5_attn<<<TT, 512, K5_SMEM_BYTES>>>(W_h, W_e, W_v, out);
}